// round 12
// baseline (speedup 1.0000x reference)
#include <cuda_runtime.h>
#include <cuda_bf16.h>
#include <math.h>
#include <stdint.h>

#define BB 8
#define CC 256
#define NN 4096   // 64*64
#define MM 1024   // 32*32
#define CI 128

typedef __nv_bfloat16 bf16;

// ---------------- scratch (16B aligned for uint4 staging) ----------------
__device__ __align__(16) bf16 g_w3h[3*128*256];
__device__ __align__(16) bf16 g_w3l[3*128*256];
__device__ __align__(16) bf16 g_Wwh[256*128];
__device__ __align__(16) bf16 g_Wwl[256*128];
__device__ __align__(16) bf16 g_Qh[BB*(size_t)CI*NN];   // [b][ci][n]
__device__ __align__(16) bf16 g_Ql[BB*(size_t)CI*NN];
__device__ __align__(16) bf16 g_Kh[BB*(size_t)CI*MM];   // [b][ci][m]
__device__ __align__(16) bf16 g_Kl[BB*(size_t)CI*MM];
__device__ __align__(16) bf16 g_Vh[BB*(size_t)CI*MM];
__device__ __align__(16) bf16 g_Vl[BB*(size_t)CI*MM];
__device__ __align__(16) bf16 g_Yh[BB*(size_t)NN*CI];   // [b][n][ci]
__device__ __align__(16) bf16 g_Yl[BB*(size_t)NN*CI];
__device__ float g_Wy[BB*(size_t)CC*NN];                // [b][c][n]
__device__ float g_psum[CC*512];
__device__ float g_psq [CC*512];
__device__ float g_aff [2*CC];

// ---------------- helpers ----------------
__device__ __forceinline__ uint32_t smem_u32(const void* p) {
    uint32_t a;
    asm("{ .reg .u64 t; cvta.to.shared.u64 t, %1; cvt.u32.u64 %0, t; }" : "=r"(a) : "l"(p));
    return a;
}
__device__ __forceinline__ void ldsm_x4(uint32_t* r, uint32_t addr) {
    asm volatile("ldmatrix.sync.aligned.m8n8.x4.shared.b16 {%0,%1,%2,%3}, [%4];"
        : "=r"(r[0]), "=r"(r[1]), "=r"(r[2]), "=r"(r[3]) : "r"(addr));
}
__device__ __forceinline__ void ldsm_x4t(uint32_t* r, uint32_t addr) {
    asm volatile("ldmatrix.sync.aligned.m8n8.x4.trans.shared.b16 {%0,%1,%2,%3}, [%4];"
        : "=r"(r[0]), "=r"(r[1]), "=r"(r[2]), "=r"(r[3]) : "r"(addr));
}
__device__ __forceinline__ void mma_bf16(float* c, const uint32_t* a, const uint32_t* b) {
    asm volatile("mma.sync.aligned.m16n8k16.row.col.f32.bf16.bf16.f32 "
        "{%0,%1,%2,%3}, {%4,%5,%6,%7}, {%8,%9}, {%0,%1,%2,%3};"
        : "+f"(c[0]), "+f"(c[1]), "+f"(c[2]), "+f"(c[3])
        : "r"(a[0]), "r"(a[1]), "r"(a[2]), "r"(a[3]), "r"(b[0]), "r"(b[1]));
}
__device__ __forceinline__ uint32_t packh(bf16 a, bf16 b) {
    __nv_bfloat162 t(a, b);
    return *reinterpret_cast<uint32_t*>(&t);
}
__device__ __forceinline__ void split2(float a, float b, uint32_t& hi, uint32_t& lo) {
    bf16 ha = __float2bfloat16(a), hb = __float2bfloat16(b);
    hi = packh(ha, hb);
    lo = packh(__float2bfloat16(a - __bfloat162float(ha)),
               __float2bfloat16(b - __bfloat162float(hb)));
}
#define CPA16(dst, src) \
    asm volatile("cp.async.cg.shared.global [%0], [%1], 16;" :: "r"(dst), "l"(src))
#define CP_COMMIT() asm volatile("cp.async.commit_group;")
#define CP_WAIT0()  asm volatile("cp.async.wait_group 0;")
#define CP_WAIT1()  asm volatile("cp.async.wait_group 1;")

// =====================================================================
// prep: weight fp32 -> bf16 hi/lo (4 matrices, one launch)
// =====================================================================
__global__ __launch_bounds__(256) void prep_w4_k(
    const float* __restrict__ tw, const float* __restrict__ pw,
    const float* __restrict__ gw, const float* __restrict__ Ww)
{
    int seg = blockIdx.x >> 5;
    int i4 = (blockIdx.x & 31) * 256 + threadIdx.x;   // 0..8191
    const float* src = (seg == 0) ? tw : (seg == 1) ? pw : (seg == 2) ? gw : Ww;
    bf16* hi = (seg == 3) ? g_Wwh : g_w3h + seg * 32768;
    bf16* lo = (seg == 3) ? g_Wwl : g_w3l + seg * 32768;
    float4 v = ((const float4*)src)[i4];
    uint32_t h0, l0, h1, l1;
    split2(v.x, v.y, h0, l0);
    split2(v.z, v.w, h1, l1);
    ((uint2*)hi)[i4] = make_uint2(h0, h1);
    ((uint2*)lo)[i4] = make_uint2(l0, l1);
}

// =====================================================================
// fused QKV conv (HMMA): out[o][n] = bias[o] + sum_c w[o][c] x[c][n]
// x is fp32, split to hi/lo in-kernel during staging.
// grid (32 n-tiles, 8 b, 3 sel); CTA 256 thr, m=128 o, n=128.
// =====================================================================
#define WSTR 40
#define XSTR 136
#define CONV_SMEM 37888

__global__ __launch_bounds__(256, 2) void conv_hmma_k(
    const float* __restrict__ x,
    const float* __restrict__ tb, const float* __restrict__ pb2,
    const float* __restrict__ gb)
{
    extern __shared__ char cs[];
    bf16* swh = (bf16*)cs;
    bf16* swl = (bf16*)(cs + 10240);
    bf16* sxh = (bf16*)(cs + 20480);
    bf16* sxl = (bf16*)(cs + 29184);
    float* pbuf = (float*)cs;
    uint32_t sb = smem_u32(cs);

    int tid = threadIdx.x;
    int lane = tid & 31, w = tid >> 5;
    int wy = w >> 1, wx = w & 1;
    int i8 = lane & 7, quad = lane >> 3, r0 = lane >> 2, cq = (lane & 3) * 2;
    int bx = blockIdx.x, b = blockIdx.y, sel = blockIdx.z;

    const bf16* wh = g_w3h + sel * 32768;
    const bf16* wl = g_w3l + sel * 32768;
    const float* bias = (sel == 0) ? tb : (sel == 1) ? pb2 : gb;

    float acc[2][8][4];
#pragma unroll
    for (int mt = 0; mt < 2; mt++) {
        float bv0 = bias[wy*32 + mt*16 + r0];
        float bv1 = bias[wy*32 + mt*16 + r0 + 8];
#pragma unroll
        for (int j = 0; j < 8; j++) {
            acc[mt][j][0] = bv0; acc[mt][j][1] = bv0;
            acc[mt][j][2] = bv1; acc[mt][j][3] = bv1;
        }
    }

    for (int ks = 0; ks < 8; ks++) {
        int c0 = ks * 32;
        {   // stage w [128][32] hi/lo (two row-halves per thread)
            int row = tid >> 2, ch = tid & 3;
            *(uint4*)(swh + row*WSTR + ch*8) = *(const uint4*)(wh + row*256 + c0 + ch*8);
            *(uint4*)(swl + row*WSTR + ch*8) = *(const uint4*)(wl + row*256 + c0 + ch*8);
            row += 64;
            *(uint4*)(swh + row*WSTR + ch*8) = *(const uint4*)(wh + row*256 + c0 + ch*8);
            *(uint4*)(swl + row*WSTR + ch*8) = *(const uint4*)(wl + row*256 + c0 + ch*8);
        }
        {   // stage x [32][128]: fp32 -> bf16 hi/lo in-flight
            int row = tid >> 4, ch = tid & 15;
#pragma unroll
            for (int rh = 0; rh < 2; rh++) {
                const float* xp = x + ((size_t)(b*CC + c0 + row))*NN + bx*128 + ch*8;
                float4 v0 = *(const float4*)xp;
                float4 v1 = *(const float4*)(xp + 4);
                uint32_t h0, lo0, h1, lo1, h2, lo2, h3, lo3;
                split2(v0.x, v0.y, h0, lo0);
                split2(v0.z, v0.w, h1, lo1);
                split2(v1.x, v1.y, h2, lo2);
                split2(v1.z, v1.w, h3, lo3);
                *(uint2*)(sxh + row*XSTR + ch*8)     = make_uint2(h0, h1);
                *(uint2*)(sxh + row*XSTR + ch*8 + 4) = make_uint2(h2, h3);
                *(uint2*)(sxl + row*XSTR + ch*8)     = make_uint2(lo0, lo1);
                *(uint2*)(sxl + row*XSTR + ch*8 + 4) = make_uint2(lo2, lo3);
                row += 16;
            }
        }
        __syncthreads();

#pragma unroll
        for (int kc = 0; kc < 2; kc++) {
            uint32_t ahi[2][4], alo[2][4];
#pragma unroll
            for (int mt = 0; mt < 2; mt++) {
                uint32_t ao = ((wy*32 + mt*16 + i8 + (quad&1)*8) * WSTR + kc*16 + (quad>>1)*8) * 2;
                ldsm_x4(ahi[mt], sb + ao);
                ldsm_x4(alo[mt], sb + 10240 + ao);
            }
#pragma unroll
            for (int j2 = 0; j2 < 4; j2++) {
                uint32_t bo = ((kc*16 + i8 + (quad&1)*8) * XSTR + wx*64 + j2*16 + (quad>>1)*8) * 2;
                uint32_t bhi[4], blo[4];
                ldsm_x4t(bhi, sb + 20480 + bo);
                ldsm_x4t(blo, sb + 29184 + bo);
#pragma unroll
                for (int mt = 0; mt < 2; mt++) {
                    mma_bf16(acc[mt][j2*2],   ahi[mt], bhi);
                    mma_bf16(acc[mt][j2*2],   ahi[mt], blo);
                    mma_bf16(acc[mt][j2*2],   alo[mt], bhi);
                    mma_bf16(acc[mt][j2*2+1], ahi[mt], bhi+2);
                    mma_bf16(acc[mt][j2*2+1], ahi[mt], blo+2);
                    mma_bf16(acc[mt][j2*2+1], alo[mt], bhi+2);
                }
            }
        }
        __syncthreads();
    }

    if (sel == 0) {
#pragma unroll
        for (int mt = 0; mt < 2; mt++) {
            int ci0 = wy*32 + mt*16 + r0;
#pragma unroll
            for (int j = 0; j < 8; j++) {
                int n = bx*128 + wx*64 + j*8 + cq;
                uint32_t h, l;
                split2(acc[mt][j][0], acc[mt][j][1], h, l);
                size_t o0 = ((size_t)(b*CI + ci0))*NN + n;
                *(uint32_t*)(g_Qh + o0) = h;
                *(uint32_t*)(g_Ql + o0) = l;
                split2(acc[mt][j][2], acc[mt][j][3], h, l);
                size_t o1 = ((size_t)(b*CI + ci0 + 8))*NN + n;
                *(uint32_t*)(g_Qh + o1) = h;
                *(uint32_t*)(g_Ql + o1) = l;
            }
        }
    } else {
        bf16* outH = (sel == 1) ? g_Kh : g_Vh;
        bf16* outL = (sel == 1) ? g_Kl : g_Vl;
        float hv[2][2][8];
#pragma unroll
        for (int mt = 0; mt < 2; mt++)
#pragma unroll
            for (int j = 0; j < 8; j++) {
                hv[mt][0][j] = fmaxf(acc[mt][j][0], acc[mt][j][1]);
                hv[mt][1][j] = fmaxf(acc[mt][j][2], acc[mt][j][3]);
            }
        int wp = (lane & 3);
        if (wx == 1) {
#pragma unroll
            for (int mt = 0; mt < 2; mt++)
#pragma unroll
                for (int j = 0; j < 8; j++) {
                    pbuf[(wy*32 + mt*16 + r0)     * 33 + j*4 + wp] = hv[mt][0][j];
                    pbuf[(wy*32 + mt*16 + r0 + 8) * 33 + j*4 + wp] = hv[mt][1][j];
                }
        }
        __syncthreads();
        if (wx == 0) {
#pragma unroll
            for (int mt = 0; mt < 2; mt++)
#pragma unroll
                for (int h2 = 0; h2 < 2; h2++) {
                    int ci0 = wy*32 + mt*16 + r0 + h2*8;
#pragma unroll
                    for (int j = 0; j < 8; j++) {
                        float v = fmaxf(hv[mt][h2][j], pbuf[ci0 * 33 + j*4 + wp]);
                        bf16 hb = __float2bfloat16(v);
                        bf16 lb = __float2bfloat16(v - __bfloat162float(hb));
                        size_t off = ((size_t)(b*CI + ci0))*MM + bx*32 + j*4 + wp;
                        outH[off] = hb;
                        outL[off] = lb;
                    }
                }
        }
    }
}

// =====================================================================
// HMMA flash attention, Bc=64, cp.async double-buffered K/V pipeline,
// softmax exp interleaved with PV per k-chunk.
// grid (32 q-tiles, 8 b), 256 thr. P in registers, no max-subtract.
// =====================================================================
#define QSTR 136
#define KSTR 72
#define O_QH 0
#define O_QL 17408
#define KV_BASE 34816          // elems
#define KV_STG  36864          // elems per stage (4 arrays x 128 x 72)
#define ATTN_SMEM ((KV_BASE + 2*KV_STG) * 2)   // 217,088 B

__global__ __launch_bounds__(256, 1) void attn_k2()
{
    extern __shared__ bf16 sm[];
    uint32_t sb = smem_u32(sm);
    int tid = threadIdx.x;
    int lane = tid & 31, w = tid >> 5;
    int i8 = lane & 7, quad = lane >> 3, r0 = lane >> 2, cq = (lane & 3) * 2;
    int b = blockIdx.y, q0 = blockIdx.x * 128;

    // ---- prefetch Q + tile0 (group 0)
    {
        int row = tid >> 4, ch = tid & 15;   // Q: 2 arrays x 128r x 16ch
#pragma unroll
        for (int rh = 0; rh < 8; rh++) {
            size_t src = ((size_t)(b*CI + row))*NN + q0 + ch*8;
            CPA16(sb + (O_QH + row*QSTR + ch*8)*2, (const void*)(g_Qh + src));
            CPA16(sb + (O_QL + row*QSTR + ch*8)*2, (const void*)(g_Ql + src));
            row += 16;
        }
    }
    {
        // tile0 K/V: 4 arrays x 128r x 8ch
        for (int i = 0; i < 16; i++) {
            int idx = tid + i * 256;          // 0..4095
            int arr = idx >> 10, within = idx & 1023;
            int row = within >> 3, ch = within & 7;
            const bf16* srcp = (arr == 0) ? g_Kh : (arr == 1) ? g_Kl : (arr == 2) ? g_Vh : g_Vl;
            size_t src = ((size_t)(b*CI + row))*MM + 0 + ch*8;
            CPA16(sb + (KV_BASE + arr*9216 + row*KSTR + ch*8)*2, (const void*)(srcp + src));
        }
    }
    CP_COMMIT();

    float oacc[16][4];
#pragma unroll
    for (int j = 0; j < 16; j++)
#pragma unroll
        for (int c = 0; c < 4; c++) oacc[j][c] = 0.f;
    float l0 = 0.f, l1 = 0.f;

    for (int t = 0; t < 16; t++) {
        int cur = t & 1;
        // ---- prefetch next tile into alt buffer
        if (t < 15) {
            int m0 = (t + 1) * 64;
            uint32_t dstb = sb + (KV_BASE + (cur ^ 1) * KV_STG) * 2;
            for (int i = 0; i < 16; i++) {
                int idx = tid + i * 256;
                int arr = idx >> 10, within = idx & 1023;
                int row = within >> 3, ch = within & 7;
                const bf16* srcp = (arr == 0) ? g_Kh : (arr == 1) ? g_Kl : (arr == 2) ? g_Vh : g_Vl;
                size_t src = ((size_t)(b*CI + row))*MM + m0 + ch*8;
                CPA16(dstb + (arr*9216 + row*KSTR + ch*8)*2, (const void*)(srcp + src));
            }
            CP_COMMIT();
            CP_WAIT1();
        } else {
            CP_WAIT0();
        }
        __syncthreads();   // staged data visible to all

        uint32_t kb = sb + (KV_BASE + cur * KV_STG) * 2;

        // ---- S = Q K^T : 16q x 64k per warp
        float sacc[8][4];
#pragma unroll
        for (int j = 0; j < 8; j++)
#pragma unroll
            for (int c = 0; c < 4; c++) sacc[j][c] = 0.f;

#pragma unroll
        for (int d0 = 0; d0 < 8; d0++) {
            uint32_t ahi[4], alo[4];
            uint32_t ao = ((d0*16 + (quad>>1)*8 + i8) * QSTR + w*16 + (quad&1)*8) * 2;
            ldsm_x4t(ahi, sb + O_QH*2 + ao);
            ldsm_x4t(alo, sb + O_QL*2 + ao);
#pragma unroll
            for (int j2 = 0; j2 < 4; j2++) {
                uint32_t bo = ((d0*16 + i8 + (quad&1)*8) * KSTR + j2*16 + (quad>>1)*8) * 2;
                uint32_t bhi[4], blo[4];
                ldsm_x4t(bhi, kb + bo);              // Kh
                ldsm_x4t(blo, kb + 9216*2 + bo);     // Kl
                mma_bf16(sacc[j2*2],   ahi, bhi);
                mma_bf16(sacc[j2*2],   ahi, blo);
                mma_bf16(sacc[j2*2],   alo, bhi);
                mma_bf16(sacc[j2*2+1], ahi, bhi+2);
                mma_bf16(sacc[j2*2+1], ahi, blo+2);
                mma_bf16(sacc[j2*2+1], alo, bhi+2);
            }
        }

        // ---- interleaved: per k-chunk exp(S) -> PV MMAs
#pragma unroll
        for (int kc = 0; kc < 4; kc++) {
            uint32_t aph[4], apl[4];
#pragma unroll
            for (int h2 = 0; h2 < 2; h2++) {
                int j = kc*2 + h2;
                float p0 = __expf(sacc[j][0]), p1 = __expf(sacc[j][1]);
                float p2 = __expf(sacc[j][2]), p3 = __expf(sacc[j][3]);
                l0 += p0 + p1;
                l1 += p2 + p3;
                split2(p0, p1, aph[h2*2],   apl[h2*2]);
                split2(p2, p3, aph[h2*2+1], apl[h2*2+1]);
            }
#pragma unroll
            for (int j2 = 0; j2 < 8; j2++) {
                uint32_t bo = ((j2*16 + i8 + (quad>>1)*8) * KSTR + kc*16 + (quad&1)*8) * 2;
                uint32_t bhi[4], blo[4];
                ldsm_x4(bhi, kb + 18432*2 + bo);     // Vh
                ldsm_x4(blo, kb + 27648*2 + bo);     // Vl
                mma_bf16(oacc[j2*2],   aph, bhi);
                mma_bf16(oacc[j2*2],   aph, blo);
                mma_bf16(oacc[j2*2],   apl, bhi);
                mma_bf16(oacc[j2*2+1], aph, bhi+2);
                mma_bf16(oacc[j2*2+1], aph, blo+2);
                mma_bf16(oacc[j2*2+1], apl, bhi+2);
            }
        }
        __syncthreads();   // compute done before this buffer is re-prefetched
    }

    // ---- finalize: O/l -> Y bf16 hi/lo [b][n][ci]
    l0 += __shfl_xor_sync(0xffffffffu, l0, 1);
    l0 += __shfl_xor_sync(0xffffffffu, l0, 2);
    l1 += __shfl_xor_sync(0xffffffffu, l1, 1);
    l1 += __shfl_xor_sync(0xffffffffu, l1, 2);
    float inv0 = 1.f / l0, inv1 = 1.f / l1;

    int qr = q0 + w*16 + r0;
#pragma unroll
    for (int j = 0; j < 16; j++) {
        int ci = j*8 + cq;
        uint32_t h, l;
        split2(oacc[j][0] * inv0, oacc[j][1] * inv0, h, l);
        size_t o0 = ((size_t)(b*NN + qr))*CI + ci;
        *(uint32_t*)(g_Yh + o0) = h;
        *(uint32_t*)(g_Yl + o0) = l;
        split2(oacc[j][2] * inv1, oacc[j][3] * inv1, h, l);
        size_t o1 = ((size_t)(b*NN + qr + 8))*CI + ci;
        *(uint32_t*)(g_Yh + o1) = h;
        *(uint32_t*)(g_Yl + o1) = l;
    }
}

// =====================================================================
// W conv (HMMA) + BN partials
// =====================================================================
__global__ __launch_bounds__(256, 2) void wconv_hmma_k(const float* __restrict__ bias)
{
    __shared__ bf16 swh[128*WSTR];
    __shared__ bf16 swl[128*WSTR];
    __shared__ bf16 syh[128*WSTR];
    __shared__ bf16 syl[128*WSTR];
    uint32_t a_wh = smem_u32(swh), a_wl = smem_u32(swl);
    uint32_t a_yh = smem_u32(syh), a_yl = smem_u32(syl);

    int tid = threadIdx.x;
    int lane = tid & 31, w = tid >> 5;
    int wy = w >> 1, wx = w & 1;
    int i8 = lane & 7, quad = lane >> 3, r0 = lane >> 2, cq = (lane & 3) * 2;
    int nt = blockIdx.x, ct = blockIdx.y, b = blockIdx.z;
    int c0 = ct * 128, n0 = nt * 128;

    float acc[2][8][4];
#pragma unroll
    for (int mt = 0; mt < 2; mt++) {
        float bv0 = bias[c0 + wy*32 + mt*16 + r0];
        float bv1 = bias[c0 + wy*32 + mt*16 + r0 + 8];
#pragma unroll
        for (int j = 0; j < 8; j++) {
            acc[mt][j][0] = bv0; acc[mt][j][1] = bv0;
            acc[mt][j][2] = bv1; acc[mt][j][3] = bv1;
        }
    }

    for (int ks = 0; ks < 4; ks++) {
        {
            int row = tid >> 2, ch = tid & 3;
#pragma unroll
            for (int rh = 0; rh < 2; rh++) {
                *(uint4*)(swh + row*WSTR + ch*8) = *(const uint4*)(g_Wwh + (c0 + row)*CI + ks*32 + ch*8);
                *(uint4*)(swl + row*WSTR + ch*8) = *(const uint4*)(g_Wwl + (c0 + row)*CI + ks*32 + ch*8);
                size_t src = ((size_t)(b*NN + n0 + row))*CI + ks*32 + ch*8;
                *(uint4*)(syh + row*WSTR + ch*8) = *(const uint4*)(g_Yh + src);
                *(uint4*)(syl + row*WSTR + ch*8) = *(const uint4*)(g_Yl + src);
                row += 64;
            }
        }
        __syncthreads();
#pragma unroll
        for (int kc = 0; kc < 2; kc++) {
            uint32_t ahi[2][4], alo[2][4];
#pragma unroll
            for (int mt = 0; mt < 2; mt++) {
                uint32_t ao = ((wy*32 + mt*16 + i8 + (quad&1)*8) * WSTR + kc*16 + (quad>>1)*8) * 2;
                ldsm_x4(ahi[mt], a_wh + ao);
                ldsm_x4(alo[mt], a_wl + ao);
            }
#pragma unroll
            for (int j2 = 0; j2 < 4; j2++) {
                uint32_t bo = ((wx*64 + j2*16 + i8 + (quad>>1)*8) * WSTR + kc*16 + (quad&1)*8) * 2;
                uint32_t bhi[4], blo[4];
                ldsm_x4(bhi, a_yh + bo);
                ldsm_x4(blo, a_yl + bo);
#pragma unroll
                for (int mt = 0; mt < 2; mt++) {
                    mma_bf16(acc[mt][j2*2],   ahi[mt], bhi);
                    mma_bf16(acc[mt][j2*2],   ahi[mt], blo);
                    mma_bf16(acc[mt][j2*2],   alo[mt], bhi);
                    mma_bf16(acc[mt][j2*2+1], ahi[mt], bhi+2);
                    mma_bf16(acc[mt][j2*2+1], ahi[mt], blo+2);
                    mma_bf16(acc[mt][j2*2+1], alo[mt], bhi+2);
                }
            }
        }
        __syncthreads();
    }

#pragma unroll
    for (int mt = 0; mt < 2; mt++) {
#pragma unroll
        for (int h2 = 0; h2 < 2; h2++) {
            int c = c0 + wy*32 + mt*16 + r0 + h2*8;
            float s = 0.f, sq = 0.f;
#pragma unroll
            for (int j = 0; j < 8; j++) {
                float v0 = acc[mt][j][h2*2], v1 = acc[mt][j][h2*2+1];
                s += v0 + v1;
                sq += v0*v0 + v1*v1;
                size_t off = ((size_t)(b*CC + c))*NN + n0 + wx*64 + j*8 + cq;
                *(float2*)(g_Wy + off) = make_float2(v0, v1);
            }
            s  += __shfl_xor_sync(0xffffffffu, s, 1);
            s  += __shfl_xor_sync(0xffffffffu, s, 2);
            sq += __shfl_xor_sync(0xffffffffu, sq, 1);
            sq += __shfl_xor_sync(0xffffffffu, sq, 2);
            if ((lane & 3) == 0) {
                g_psum[c * 512 + b * 64 + nt * 2 + wx] = s;
                g_psq [c * 512 + b * 64 + nt * 2 + wx] = sq;
            }
        }
    }
}

// ---------------- BN stats reduce (deterministic) ----------------
__global__ __launch_bounds__(256) void bnstats_k(
    const float* __restrict__ gamma, const float* __restrict__ beta)
{
    __shared__ double sd[256], sqd[256];
    int c = blockIdx.x, t = threadIdx.x;
    double s  = (double)g_psum[c*512 + t] + (double)g_psum[c*512 + 256 + t];
    double sq = (double)g_psq [c*512 + t] + (double)g_psq [c*512 + 256 + t];
    sd[t] = s; sqd[t] = sq;
    __syncthreads();
    for (int off = 128; off; off >>= 1) {
        if (t < off) { sd[t] += sd[t+off]; sqd[t] += sqd[t+off]; }
        __syncthreads();
    }
    if (t == 0) {
        const double cnt = (double)BB * NN;
        double mean = sd[0] / cnt;
        double var  = sqd[0] / cnt - mean * mean;
        float inv = rsqrtf((float)var + 1e-5f);
        float a = gamma[c] * inv;
        g_aff[c]      = a;
        g_aff[CC + c] = beta[c] - (float)mean * a;
    }
}

// ---------------- final: out = Wy*a[c] + b2[c] + x ----------------
__global__ __launch_bounds__(256) void final_k(
    const float* __restrict__ x, float* __restrict__ out)
{
    int i = blockIdx.x * blockDim.x + threadIdx.x;
    if (i < BB * CC * NN) {
        int c = (i >> 12) & 255;
        out[i] = g_Wy[i] * g_aff[c] + g_aff[CC + c] + x[i];
    }
}

// ---------------- launch ----------------
extern "C" void kernel_launch(void* const* d_in, const int* in_sizes, int n_in,
                              void* d_out, int out_size)
{
    const float* x       = (const float*)d_in[0];
    const float* theta_w = (const float*)d_in[1];
    const float* theta_b = (const float*)d_in[2];
    const float* phi_w   = (const float*)d_in[3];
    const float* phi_b   = (const float*)d_in[4];
    const float* g_w     = (const float*)d_in[5];
    const float* g_b     = (const float*)d_in[6];
    const float* W_w     = (const float*)d_in[7];
    const float* W_b     = (const float*)d_in[8];
    const float* bn_g    = (const float*)d_in[9];
    const float* bn_b    = (const float*)d_in[10];
    float* out = (float*)d_out;

    cudaFuncSetAttribute(attn_k2, cudaFuncAttributeMaxDynamicSharedMemorySize, ATTN_SMEM);

    prep_w4_k<<<128, 256>>>(theta_w, phi_w, g_w, W_w);

    conv_hmma_k<<<dim3(32, 8, 3), 256, CONV_SMEM>>>(x, theta_b, phi_b, g_b);
    attn_k2<<<dim3(32, 8), 256, ATTN_SMEM>>>();
    wconv_hmma_k<<<dim3(32, 2, 8), 256>>>(W_b);
    bnstats_k<<<CC, 256>>>(bn_g, bn_b);

    int tot = BB * CC * NN;
    final_k<<<(tot + 255) / 256, 256>>>(x, out);
}

// round 16
// speedup vs baseline: 1.4630x; 1.4630x over previous
#include <cuda_runtime.h>
#include <cuda_bf16.h>
#include <math.h>
#include <stdint.h>

#define BB 8
#define CC 256
#define NN 4096   // 64*64
#define MM 1024   // 32*32
#define CI 128

typedef __nv_bfloat16 bf16;

// ---------------- scratch (16B aligned for uint4 staging) ----------------
__device__ __align__(16) bf16 g_xh[BB*(size_t)CC*NN];
__device__ __align__(16) bf16 g_xl[BB*(size_t)CC*NN];
__device__ __align__(16) bf16 g_w3h[3*128*256];
__device__ __align__(16) bf16 g_w3l[3*128*256];
__device__ __align__(16) bf16 g_Wwh[256*128];
__device__ __align__(16) bf16 g_Wwl[256*128];
__device__ __align__(16) bf16 g_Qh[BB*(size_t)CI*NN];   // [b][ci][n]
__device__ __align__(16) bf16 g_Ql[BB*(size_t)CI*NN];
__device__ __align__(16) bf16 g_Kh[BB*(size_t)CI*MM];   // [b][ci][m]
__device__ __align__(16) bf16 g_Kl[BB*(size_t)CI*MM];
__device__ __align__(16) bf16 g_Vh[BB*(size_t)CI*MM];
__device__ __align__(16) bf16 g_Vl[BB*(size_t)CI*MM];
__device__ __align__(16) bf16 g_Yh[BB*(size_t)NN*CI];   // [b][n][ci]
__device__ __align__(16) bf16 g_Yl[BB*(size_t)NN*CI];
__device__ float g_Wy[BB*(size_t)CC*NN];                // [b][c][n]
__device__ float g_psum[CC*512];
__device__ float g_psq [CC*512];
__device__ float g_aff [2*CC];

// ---------------- helpers ----------------
__device__ __forceinline__ uint32_t smem_u32(const void* p) {
    uint32_t a;
    asm("{ .reg .u64 t; cvta.to.shared.u64 t, %1; cvt.u32.u64 %0, t; }" : "=r"(a) : "l"(p));
    return a;
}
__device__ __forceinline__ void ldsm_x4(uint32_t* r, uint32_t addr) {
    asm volatile("ldmatrix.sync.aligned.m8n8.x4.shared.b16 {%0,%1,%2,%3}, [%4];"
        : "=r"(r[0]), "=r"(r[1]), "=r"(r[2]), "=r"(r[3]) : "r"(addr));
}
__device__ __forceinline__ void ldsm_x4t(uint32_t* r, uint32_t addr) {
    asm volatile("ldmatrix.sync.aligned.m8n8.x4.trans.shared.b16 {%0,%1,%2,%3}, [%4];"
        : "=r"(r[0]), "=r"(r[1]), "=r"(r[2]), "=r"(r[3]) : "r"(addr));
}
__device__ __forceinline__ void mma_bf16(float* c, const uint32_t* a, const uint32_t* b) {
    asm volatile("mma.sync.aligned.m16n8k16.row.col.f32.bf16.bf16.f32 "
        "{%0,%1,%2,%3}, {%4,%5,%6,%7}, {%8,%9}, {%0,%1,%2,%3};"
        : "+f"(c[0]), "+f"(c[1]), "+f"(c[2]), "+f"(c[3])
        : "r"(a[0]), "r"(a[1]), "r"(a[2]), "r"(a[3]), "r"(b[0]), "r"(b[1]));
}
__device__ __forceinline__ uint32_t packh(bf16 a, bf16 b) {
    __nv_bfloat162 t(a, b);
    return *reinterpret_cast<uint32_t*>(&t);
}
__device__ __forceinline__ void split2(float a, float b, uint32_t& hi, uint32_t& lo) {
    bf16 ha = __float2bfloat16(a), hb = __float2bfloat16(b);
    hi = packh(ha, hb);
    lo = packh(__float2bfloat16(a - __bfloat162float(ha)),
               __float2bfloat16(b - __bfloat162float(hb)));
}
#define CPA16(dst, src) \
    asm volatile("cp.async.cg.shared.global [%0], [%1], 16;" :: "r"(dst), "l"(src))
#define CP_COMMIT() asm volatile("cp.async.commit_group;")
#define CP_WAIT0()  asm volatile("cp.async.wait_group 0;")
#define CP_WAIT1()  asm volatile("cp.async.wait_group 1;")

// =====================================================================
// prep kernels: fp32 -> bf16 hi/lo
// =====================================================================
__global__ __launch_bounds__(256) void prep_x_k(const float* __restrict__ x) {
    size_t i4 = (size_t)blockIdx.x * 256 + threadIdx.x;
    if (i4 >= (size_t)BB * CC * NN / 4) return;
    float4 v = ((const float4*)x)[i4];
    uint32_t h0, l0, h1, l1;
    split2(v.x, v.y, h0, l0);
    split2(v.z, v.w, h1, l1);
    ((uint2*)g_xh)[i4] = make_uint2(h0, h1);
    ((uint2*)g_xl)[i4] = make_uint2(l0, l1);
}
__global__ __launch_bounds__(256) void prep_w4_k(
    const float* __restrict__ tw, const float* __restrict__ pw,
    const float* __restrict__ gw, const float* __restrict__ Ww)
{
    int seg = blockIdx.x >> 5;
    int i4 = (blockIdx.x & 31) * 256 + threadIdx.x;   // 0..8191
    const float* src = (seg == 0) ? tw : (seg == 1) ? pw : (seg == 2) ? gw : Ww;
    bf16* hi = (seg == 3) ? g_Wwh : g_w3h + seg * 32768;
    bf16* lo = (seg == 3) ? g_Wwl : g_w3l + seg * 32768;
    float4 v = ((const float4*)src)[i4];
    uint32_t h0, l0, h1, l1;
    split2(v.x, v.y, h0, l0);
    split2(v.z, v.w, h1, l1);
    ((uint2*)hi)[i4] = make_uint2(h0, h1);
    ((uint2*)lo)[i4] = make_uint2(l0, l1);
}

// =====================================================================
// fused QKV conv (HMMA) — R11 version (reads pre-split g_xh/g_xl)
// =====================================================================
#define WSTR 40
#define XSTR 136
#define CONV_SMEM 37888

__global__ __launch_bounds__(256, 2) void conv_hmma_k(
    const float* __restrict__ tb, const float* __restrict__ pb2,
    const float* __restrict__ gb)
{
    extern __shared__ char cs[];
    bf16* swh = (bf16*)cs;
    bf16* swl = (bf16*)(cs + 10240);
    bf16* sxh = (bf16*)(cs + 20480);
    bf16* sxl = (bf16*)(cs + 29184);
    float* pbuf = (float*)cs;
    uint32_t sb = smem_u32(cs);

    int tid = threadIdx.x;
    int lane = tid & 31, w = tid >> 5;
    int wy = w >> 1, wx = w & 1;
    int i8 = lane & 7, quad = lane >> 3, r0 = lane >> 2, cq = (lane & 3) * 2;
    int bx = blockIdx.x, b = blockIdx.y, sel = blockIdx.z;

    const bf16* wh = g_w3h + sel * 32768;
    const bf16* wl = g_w3l + sel * 32768;
    const float* bias = (sel == 0) ? tb : (sel == 1) ? pb2 : gb;

    float acc[2][8][4];
#pragma unroll
    for (int mt = 0; mt < 2; mt++) {
        float bv0 = bias[wy*32 + mt*16 + r0];
        float bv1 = bias[wy*32 + mt*16 + r0 + 8];
#pragma unroll
        for (int j = 0; j < 8; j++) {
            acc[mt][j][0] = bv0; acc[mt][j][1] = bv0;
            acc[mt][j][2] = bv1; acc[mt][j][3] = bv1;
        }
    }

    for (int ks = 0; ks < 8; ks++) {
        int c0 = ks * 32;
        {
            int row = tid >> 2, ch = tid & 3;
            *(uint4*)(swh + row*WSTR + ch*8) = *(const uint4*)(wh + row*256 + c0 + ch*8);
            *(uint4*)(swl + row*WSTR + ch*8) = *(const uint4*)(wl + row*256 + c0 + ch*8);
            row += 64;
            *(uint4*)(swh + row*WSTR + ch*8) = *(const uint4*)(wh + row*256 + c0 + ch*8);
            *(uint4*)(swl + row*WSTR + ch*8) = *(const uint4*)(wl + row*256 + c0 + ch*8);
        }
        {
            int row = tid >> 4, ch = tid & 15;
            size_t src = ((size_t)(b*CC + c0 + row))*NN + bx*128 + ch*8;
            *(uint4*)(sxh + row*XSTR + ch*8) = *(const uint4*)(g_xh + src);
            *(uint4*)(sxl + row*XSTR + ch*8) = *(const uint4*)(g_xl + src);
            row += 16;
            src = ((size_t)(b*CC + c0 + row))*NN + bx*128 + ch*8;
            *(uint4*)(sxh + row*XSTR + ch*8) = *(const uint4*)(g_xh + src);
            *(uint4*)(sxl + row*XSTR + ch*8) = *(const uint4*)(g_xl + src);
        }
        __syncthreads();

#pragma unroll
        for (int kc = 0; kc < 2; kc++) {
            uint32_t ahi[2][4], alo[2][4];
#pragma unroll
            for (int mt = 0; mt < 2; mt++) {
                uint32_t ao = ((wy*32 + mt*16 + i8 + (quad&1)*8) * WSTR + kc*16 + (quad>>1)*8) * 2;
                ldsm_x4(ahi[mt], sb + ao);
                ldsm_x4(alo[mt], sb + 10240 + ao);
            }
#pragma unroll
            for (int j2 = 0; j2 < 4; j2++) {
                uint32_t bo = ((kc*16 + i8 + (quad&1)*8) * XSTR + wx*64 + j2*16 + (quad>>1)*8) * 2;
                uint32_t bhi[4], blo[4];
                ldsm_x4t(bhi, sb + 20480 + bo);
                ldsm_x4t(blo, sb + 29184 + bo);
#pragma unroll
                for (int mt = 0; mt < 2; mt++) {
                    mma_bf16(acc[mt][j2*2],   ahi[mt], bhi);
                    mma_bf16(acc[mt][j2*2],   ahi[mt], blo);
                    mma_bf16(acc[mt][j2*2],   alo[mt], bhi);
                    mma_bf16(acc[mt][j2*2+1], ahi[mt], bhi+2);
                    mma_bf16(acc[mt][j2*2+1], ahi[mt], blo+2);
                    mma_bf16(acc[mt][j2*2+1], alo[mt], bhi+2);
                }
            }
        }
        __syncthreads();
    }

    if (sel == 0) {
#pragma unroll
        for (int mt = 0; mt < 2; mt++) {
            int ci0 = wy*32 + mt*16 + r0;
#pragma unroll
            for (int j = 0; j < 8; j++) {
                int n = bx*128 + wx*64 + j*8 + cq;
                uint32_t h, l;
                split2(acc[mt][j][0], acc[mt][j][1], h, l);
                size_t o0 = ((size_t)(b*CI + ci0))*NN + n;
                *(uint32_t*)(g_Qh + o0) = h;
                *(uint32_t*)(g_Ql + o0) = l;
                split2(acc[mt][j][2], acc[mt][j][3], h, l);
                size_t o1 = ((size_t)(b*CI + ci0 + 8))*NN + n;
                *(uint32_t*)(g_Qh + o1) = h;
                *(uint32_t*)(g_Ql + o1) = l;
            }
        }
    } else {
        bf16* outH = (sel == 1) ? g_Kh : g_Vh;
        bf16* outL = (sel == 1) ? g_Kl : g_Vl;
        float hv[2][2][8];
#pragma unroll
        for (int mt = 0; mt < 2; mt++)
#pragma unroll
            for (int j = 0; j < 8; j++) {
                hv[mt][0][j] = fmaxf(acc[mt][j][0], acc[mt][j][1]);
                hv[mt][1][j] = fmaxf(acc[mt][j][2], acc[mt][j][3]);
            }
        int wp = (lane & 3);
        if (wx == 1) {
#pragma unroll
            for (int mt = 0; mt < 2; mt++)
#pragma unroll
                for (int j = 0; j < 8; j++) {
                    pbuf[(wy*32 + mt*16 + r0)     * 33 + j*4 + wp] = hv[mt][0][j];
                    pbuf[(wy*32 + mt*16 + r0 + 8) * 33 + j*4 + wp] = hv[mt][1][j];
                }
        }
        __syncthreads();
        if (wx == 0) {
#pragma unroll
            for (int mt = 0; mt < 2; mt++)
#pragma unroll
                for (int h2 = 0; h2 < 2; h2++) {
                    int ci0 = wy*32 + mt*16 + r0 + h2*8;
#pragma unroll
                    for (int j = 0; j < 8; j++) {
                        float v = fmaxf(hv[mt][h2][j], pbuf[ci0 * 33 + j*4 + wp]);
                        bf16 hb = __float2bfloat16(v);
                        bf16 lb = __float2bfloat16(v - __bfloat162float(hb));
                        size_t off = ((size_t)(b*CI + ci0))*MM + bx*32 + j*4 + wp;
                        outH[off] = hb;
                        outL[off] = lb;
                    }
                }
        }
    }
}

// =====================================================================
// HMMA flash attention — R11 version (cp.async double-buffered K/V,
// exp in separate phase, P in registers)
// =====================================================================
#define QSTR 136
#define KSTR 72
#define O_QH 0
#define O_QL 17408
#define KV_BASE 34816          // elems
#define KV_STG  36864          // elems per stage (4 arrays x 128 x 72)
#define ATTN_SMEM ((KV_BASE + 2*KV_STG) * 2)   // 217,088 B

__global__ __launch_bounds__(256, 1) void attn_k2()
{
    extern __shared__ bf16 sm[];
    uint32_t sb = smem_u32(sm);
    int tid = threadIdx.x;
    int lane = tid & 31, w = tid >> 5;
    int i8 = lane & 7, quad = lane >> 3, r0 = lane >> 2, cq = (lane & 3) * 2;
    int b = blockIdx.y, q0 = blockIdx.x * 128;

    // ---- prefetch Q + tile0 (group 0)
    {
        int row = tid >> 4, ch = tid & 15;
#pragma unroll
        for (int rh = 0; rh < 8; rh++) {
            size_t src = ((size_t)(b*CI + row))*NN + q0 + ch*8;
            CPA16(sb + (O_QH + row*QSTR + ch*8)*2, (const void*)(g_Qh + src));
            CPA16(sb + (O_QL + row*QSTR + ch*8)*2, (const void*)(g_Ql + src));
            row += 16;
        }
    }
    {
        for (int i = 0; i < 16; i++) {
            int idx = tid + i * 256;
            int arr = idx >> 10, within = idx & 1023;
            int row = within >> 3, ch = within & 7;
            const bf16* srcp = (arr == 0) ? g_Kh : (arr == 1) ? g_Kl : (arr == 2) ? g_Vh : g_Vl;
            size_t src = ((size_t)(b*CI + row))*MM + 0 + ch*8;
            CPA16(sb + (KV_BASE + arr*9216 + row*KSTR + ch*8)*2, (const void*)(srcp + src));
        }
    }
    CP_COMMIT();

    float oacc[16][4];
#pragma unroll
    for (int j = 0; j < 16; j++)
#pragma unroll
        for (int c = 0; c < 4; c++) oacc[j][c] = 0.f;
    float l0 = 0.f, l1 = 0.f;

    for (int t = 0; t < 16; t++) {
        int cur = t & 1;
        if (t < 15) {
            int m0 = (t + 1) * 64;
            uint32_t dstb = sb + (KV_BASE + (cur ^ 1) * KV_STG) * 2;
            for (int i = 0; i < 16; i++) {
                int idx = tid + i * 256;
                int arr = idx >> 10, within = idx & 1023;
                int row = within >> 3, ch = within & 7;
                const bf16* srcp = (arr == 0) ? g_Kh : (arr == 1) ? g_Kl : (arr == 2) ? g_Vh : g_Vl;
                size_t src = ((size_t)(b*CI + row))*MM + m0 + ch*8;
                CPA16(dstb + (arr*9216 + row*KSTR + ch*8)*2, (const void*)(srcp + src));
            }
            CP_COMMIT();
            CP_WAIT1();
        } else {
            CP_WAIT0();
        }
        __syncthreads();

        uint32_t kb = sb + (KV_BASE + cur * KV_STG) * 2;

        // ---- S = Q K^T : 16q x 64k per warp
        float sacc[8][4];
#pragma unroll
        for (int j = 0; j < 8; j++)
#pragma unroll
            for (int c = 0; c < 4; c++) sacc[j][c] = 0.f;

#pragma unroll
        for (int d0 = 0; d0 < 8; d0++) {
            uint32_t ahi[4], alo[4];
            uint32_t ao = ((d0*16 + (quad>>1)*8 + i8) * QSTR + w*16 + (quad&1)*8) * 2;
            ldsm_x4t(ahi, sb + O_QH*2 + ao);
            ldsm_x4t(alo, sb + O_QL*2 + ao);
#pragma unroll
            for (int j2 = 0; j2 < 4; j2++) {
                uint32_t bo = ((d0*16 + i8 + (quad&1)*8) * KSTR + j2*16 + (quad>>1)*8) * 2;
                uint32_t bhi[4], blo[4];
                ldsm_x4t(bhi, kb + bo);
                ldsm_x4t(blo, kb + 9216*2 + bo);
                mma_bf16(sacc[j2*2],   ahi, bhi);
                mma_bf16(sacc[j2*2],   ahi, blo);
                mma_bf16(sacc[j2*2],   alo, bhi);
                mma_bf16(sacc[j2*2+1], ahi, bhi+2);
                mma_bf16(sacc[j2*2+1], ahi, blo+2);
                mma_bf16(sacc[j2*2+1], alo, bhi+2);
            }
        }

        // ---- P = exp(S) in registers
        uint32_t phi[8][2], plo[8][2];
#pragma unroll
        for (int j = 0; j < 8; j++) {
            float p0 = __expf(sacc[j][0]), p1 = __expf(sacc[j][1]);
            float p2 = __expf(sacc[j][2]), p3 = __expf(sacc[j][3]);
            l0 += p0 + p1;
            l1 += p2 + p3;
            split2(p0, p1, phi[j][0], plo[j][0]);
            split2(p2, p3, phi[j][1], plo[j][1]);
        }

        // ---- O += P V : 16q x 128d per warp
#pragma unroll
        for (int kc = 0; kc < 4; kc++) {
            uint32_t aph[4] = { phi[kc*2][0], phi[kc*2][1], phi[kc*2+1][0], phi[kc*2+1][1] };
            uint32_t apl[4] = { plo[kc*2][0], plo[kc*2][1], plo[kc*2+1][0], plo[kc*2+1][1] };
#pragma unroll
            for (int j2 = 0; j2 < 8; j2++) {
                uint32_t bo = ((j2*16 + i8 + (quad>>1)*8) * KSTR + kc*16 + (quad&1)*8) * 2;
                uint32_t bhi[4], blo[4];
                ldsm_x4(bhi, kb + 18432*2 + bo);
                ldsm_x4(blo, kb + 27648*2 + bo);
                mma_bf16(oacc[j2*2],   aph, bhi);
                mma_bf16(oacc[j2*2],   aph, blo);
                mma_bf16(oacc[j2*2],   apl, bhi);
                mma_bf16(oacc[j2*2+1], aph, bhi+2);
                mma_bf16(oacc[j2*2+1], aph, blo+2);
                mma_bf16(oacc[j2*2+1], apl, bhi+2);
            }
        }
        __syncthreads();
    }

    // ---- finalize
    l0 += __shfl_xor_sync(0xffffffffu, l0, 1);
    l0 += __shfl_xor_sync(0xffffffffu, l0, 2);
    l1 += __shfl_xor_sync(0xffffffffu, l1, 1);
    l1 += __shfl_xor_sync(0xffffffffu, l1, 2);
    float inv0 = 1.f / l0, inv1 = 1.f / l1;

    int qr = q0 + w*16 + r0;
#pragma unroll
    for (int j = 0; j < 16; j++) {
        int ci = j*8 + cq;
        uint32_t h, l;
        split2(oacc[j][0] * inv0, oacc[j][1] * inv0, h, l);
        size_t o0 = ((size_t)(b*NN + qr))*CI + ci;
        *(uint32_t*)(g_Yh + o0) = h;
        *(uint32_t*)(g_Yl + o0) = l;
        split2(oacc[j][2] * inv1, oacc[j][3] * inv1, h, l);
        size_t o1 = ((size_t)(b*NN + qr + 8))*CI + ci;
        *(uint32_t*)(g_Yh + o1) = h;
        *(uint32_t*)(g_Yl + o1) = l;
    }
}

// =====================================================================
// W conv (HMMA) + BN partials — NEW: cp.async double-buffered staging
// stage = 4 arrays x [128][40] bf16 = 40960 B; 2 stages dynamic smem.
// =====================================================================
#define WC_STG 40960
#define WCONV_SMEM (2 * WC_STG)

__global__ __launch_bounds__(256, 2) void wconv_hmma_k(const float* __restrict__ bias)
{
    extern __shared__ char ws_[];
    uint32_t sb = smem_u32(ws_);

    int tid = threadIdx.x;
    int lane = tid & 31, w = tid >> 5;
    int wy = w >> 1, wx = w & 1;
    int i8 = lane & 7, quad = lane >> 3, r0 = lane >> 2, cq = (lane & 3) * 2;
    int nt = blockIdx.x, ct = blockIdx.y, b = blockIdx.z;
    int c0 = ct * 128, n0 = nt * 128;

    float acc[2][8][4];
#pragma unroll
    for (int mt = 0; mt < 2; mt++) {
        float bv0 = bias[c0 + wy*32 + mt*16 + r0];
        float bv1 = bias[c0 + wy*32 + mt*16 + r0 + 8];
#pragma unroll
        for (int j = 0; j < 8; j++) {
            acc[mt][j][0] = bv0; acc[mt][j][1] = bv0;
            acc[mt][j][2] = bv1; acc[mt][j][3] = bv1;
        }
    }

    // prefetch helper: stage ks into buffer s (4 arrays x 128 rows x 4 chunks)
    // 2048 CPA16 total -> 8 per thread
#define WC_PREFETCH(s_, ks_) do {                                              \
        uint32_t base_ = sb + (s_) * WC_STG;                                   \
        int k32_ = (ks_) * 32;                                                 \
        for (int i_ = 0; i_ < 8; i_++) {                                       \
            int idx_ = tid + i_ * 256;          /* 0..2047 */                  \
            int arr_ = idx_ >> 9, wi_ = idx_ & 511;                            \
            int row_ = wi_ >> 2, ch_ = wi_ & 3;                                \
            const bf16* sp_;                                                   \
            size_t src_;                                                       \
            if (arr_ == 0)      { sp_ = g_Wwh; src_ = (size_t)(c0 + row_)*CI + k32_ + ch_*8; } \
            else if (arr_ == 1) { sp_ = g_Wwl; src_ = (size_t)(c0 + row_)*CI + k32_ + ch_*8; } \
            else if (arr_ == 2) { sp_ = g_Yh;  src_ = ((size_t)(b*NN + n0 + row_))*CI + k32_ + ch_*8; } \
            else                { sp_ = g_Yl;  src_ = ((size_t)(b*NN + n0 + row_))*CI + k32_ + ch_*8; } \
            CPA16(base_ + (arr_*10240) + (row_*WSTR + ch_*8)*2, (const void*)(sp_ + src_)); \
        }                                                                      \
    } while (0)

    WC_PREFETCH(0, 0);
    CP_COMMIT();

    for (int ks = 0; ks < 4; ks++) {
        int cur = ks & 1;
        if (ks < 3) {
            WC_PREFETCH(cur ^ 1, ks + 1);
            CP_COMMIT();
            CP_WAIT1();
        } else {
            CP_WAIT0();
        }
        __syncthreads();

        uint32_t a_wh = sb + cur * WC_STG;
        uint32_t a_wl = a_wh + 10240;
        uint32_t a_yh = a_wh + 20480;
        uint32_t a_yl = a_wh + 30720;

#pragma unroll
        for (int kc = 0; kc < 2; kc++) {
            uint32_t ahi[2][4], alo[2][4];
#pragma unroll
            for (int mt = 0; mt < 2; mt++) {
                uint32_t ao = ((wy*32 + mt*16 + i8 + (quad&1)*8) * WSTR + kc*16 + (quad>>1)*8) * 2;
                ldsm_x4(ahi[mt], a_wh + ao);
                ldsm_x4(alo[mt], a_wl + ao);
            }
#pragma unroll
            for (int j2 = 0; j2 < 4; j2++) {
                uint32_t bo = ((wx*64 + j2*16 + i8 + (quad>>1)*8) * WSTR + kc*16 + (quad&1)*8) * 2;
                uint32_t bhi[4], blo[4];
                ldsm_x4(bhi, a_yh + bo);
                ldsm_x4(blo, a_yl + bo);
#pragma unroll
                for (int mt = 0; mt < 2; mt++) {
                    mma_bf16(acc[mt][j2*2],   ahi[mt], bhi);
                    mma_bf16(acc[mt][j2*2],   ahi[mt], blo);
                    mma_bf16(acc[mt][j2*2],   alo[mt], bhi);
                    mma_bf16(acc[mt][j2*2+1], ahi[mt], bhi+2);
                    mma_bf16(acc[mt][j2*2+1], ahi[mt], blo+2);
                    mma_bf16(acc[mt][j2*2+1], alo[mt], bhi+2);
                }
            }
        }
        __syncthreads();
    }
#undef WC_PREFETCH

    // epilogue: fp32 Wy + deterministic BN partials
#pragma unroll
    for (int mt = 0; mt < 2; mt++) {
#pragma unroll
        for (int h2 = 0; h2 < 2; h2++) {
            int c = c0 + wy*32 + mt*16 + r0 + h2*8;
            float s = 0.f, sq = 0.f;
#pragma unroll
            for (int j = 0; j < 8; j++) {
                float v0 = acc[mt][j][h2*2], v1 = acc[mt][j][h2*2+1];
                s += v0 + v1;
                sq += v0*v0 + v1*v1;
                size_t off = ((size_t)(b*CC + c))*NN + n0 + wx*64 + j*8 + cq;
                *(float2*)(g_Wy + off) = make_float2(v0, v1);
            }
            s  += __shfl_xor_sync(0xffffffffu, s, 1);
            s  += __shfl_xor_sync(0xffffffffu, s, 2);
            sq += __shfl_xor_sync(0xffffffffu, sq, 1);
            sq += __shfl_xor_sync(0xffffffffu, sq, 2);
            if ((lane & 3) == 0) {
                g_psum[c * 512 + b * 64 + nt * 2 + wx] = s;
                g_psq [c * 512 + b * 64 + nt * 2 + wx] = sq;
            }
        }
    }
}

// ---------------- BN stats reduce (deterministic) ----------------
__global__ __launch_bounds__(256) void bnstats_k(
    const float* __restrict__ gamma, const float* __restrict__ beta)
{
    __shared__ double sd[256], sqd[256];
    int c = blockIdx.x, t = threadIdx.x;
    double s  = (double)g_psum[c*512 + t] + (double)g_psum[c*512 + 256 + t];
    double sq = (double)g_psq [c*512 + t] + (double)g_psq [c*512 + 256 + t];
    sd[t] = s; sqd[t] = sq;
    __syncthreads();
    for (int off = 128; off; off >>= 1) {
        if (t < off) { sd[t] += sd[t+off]; sqd[t] += sqd[t+off]; }
        __syncthreads();
    }
    if (t == 0) {
        const double cnt = (double)BB * NN;
        double mean = sd[0] / cnt;
        double var  = sqd[0] / cnt - mean * mean;
        float inv = rsqrtf((float)var + 1e-5f);
        float a = gamma[c] * inv;
        g_aff[c]      = a;
        g_aff[CC + c] = beta[c] - (float)mean * a;
    }
}

// ---------------- final: out = Wy*a[c] + b2[c] + x ----------------
__global__ __launch_bounds__(256) void final_k(
    const float* __restrict__ x, float* __restrict__ out)
{
    int i = blockIdx.x * blockDim.x + threadIdx.x;
    if (i < BB * CC * NN) {
        int c = (i >> 12) & 255;
        out[i] = g_Wy[i] * g_aff[c] + g_aff[CC + c] + x[i];
    }
}

// ---------------- launch ----------------
extern "C" void kernel_launch(void* const* d_in, const int* in_sizes, int n_in,
                              void* d_out, int out_size)
{
    const float* x       = (const float*)d_in[0];
    const float* theta_w = (const float*)d_in[1];
    const float* theta_b = (const float*)d_in[2];
    const float* phi_w   = (const float*)d_in[3];
    const float* phi_b   = (const float*)d_in[4];
    const float* g_w     = (const float*)d_in[5];
    const float* g_b     = (const float*)d_in[6];
    const float* W_w     = (const float*)d_in[7];
    const float* W_b     = (const float*)d_in[8];
    const float* bn_g    = (const float*)d_in[9];
    const float* bn_b    = (const float*)d_in[10];
    float* out = (float*)d_out;

    cudaFuncSetAttribute(attn_k2, cudaFuncAttributeMaxDynamicSharedMemorySize, ATTN_SMEM);
    cudaFuncSetAttribute(wconv_hmma_k, cudaFuncAttributeMaxDynamicSharedMemorySize, WCONV_SMEM);

    prep_x_k<<<8192, 256>>>(x);
    prep_w4_k<<<128, 256>>>(theta_w, phi_w, g_w, W_w);

    conv_hmma_k<<<dim3(32, 8, 3), 256, CONV_SMEM>>>(theta_b, phi_b, g_b);
    attn_k2<<<dim3(32, 8), 256, ATTN_SMEM>>>();
    wconv_hmma_k<<<dim3(32, 2, 8), 256, WCONV_SMEM>>>(W_b);
    bnstats_k<<<CC, 256>>>(bn_g, bn_b);

    int tot = BB * CC * NN;
    final_k<<<(tot + 255) / 256, 256>>>(x, out);
}